// round 1
// baseline (speedup 1.0000x reference)
#include <cuda_runtime.h>

// Problem constants
#define BB      64      // batch
#define HL      8       // hat_L
#define NPTS    16      // N
#define DDIM    32      // d
#define FLAYER  512     // N*d
#define FTOT    4096    // hat_L*N*d
#define NCHUNK  16      // feature chunks per layer for Gram partials
#define CF      32      // features per chunk (FLAYER / NCHUNK)

// -------- device scratch (no allocations allowed) --------
__device__ float g_Zc[2][BB * FTOT];                 // centered Z (s, t)   : 2 MB
__device__ float g_P[3 * HL * NCHUNK * 4096];        // partial Grams       : 6 MB
__device__ float g_Gram[3 * HL * 4096];              // reduced layer Grams
__device__ float g_C[2][HL * NPTS * DDIM * DDIM];    // node covariances /63
__device__ float g_Wnum[3 * HL];                     // ||G||_F^2 per (type, t)
__device__ float g_sca[HL];
__device__ float g_sfa[HL * NPTS];

// ============================================================
// K1: center Z (both tensors) + per-layer L_sca from E variances
// grid: 40 blocks x 256 threads.
//   blocks 0..31 : 8192 feature tasks (2 tensors x 4096 features)
//   blocks 32..39: L_sca per layer t
// ============================================================
__global__ void k1_center_sca(const float* __restrict__ Zs,
                              const float* __restrict__ Es,
                              const float* __restrict__ Zt,
                              const float* __restrict__ Et) {
    int blk = blockIdx.x, tid = threadIdx.x;
    if (blk < 32) {
        int g = blk * 256 + tid;          // 0..8191
        int tensor = g >> 12;             // 0 = s, 1 = t
        int f = g & 4095;
        const float* Z = tensor ? Zt : Zs;
        float v[BB];
        float s = 0.0f;
        #pragma unroll
        for (int b = 0; b < BB; b++) {
            v[b] = Z[b * FTOT + f];
            s += v[b];
        }
        float m = s * (1.0f / (float)BB);
        float* out = g_Zc[tensor];
        #pragma unroll
        for (int b = 0; b < BB; b++)
            out[b * FTOT + f] = v[b] - m;
    } else {
        // L_sca: var over B (ddof=1) of E_s/E_t per (t, m, n)
        int t = blk - 32;
        int base = t * (NPTS * NPTS) + tid;   // tid = m*16+n, 0..255
        float ss = 0.f, sqs = 0.f, st = 0.f, sqt = 0.f;
        #pragma unroll 8
        for (int b = 0; b < BB; b++) {
            float a = Es[b * (HL * NPTS * NPTS) + base];
            ss += a; sqs += a * a;
            float c = Et[b * (HL * NPTS * NPTS) + base];
            st += c; sqt += c * c;
        }
        float var_s = (sqs - ss * ss * (1.0f / (float)BB)) * (1.0f / (float)(BB - 1));
        float var_t = (sqt - st * st * (1.0f / (float)BB)) * (1.0f / (float)(BB - 1));
        float d = var_s - var_t;
        float val = d * d * 0.25f;
        __shared__ float red[256];
        red[tid] = val;
        __syncthreads();
        for (int s2 = 128; s2 > 0; s2 >>= 1) {
            if (tid < s2) red[tid] += red[tid + s2];
            __syncthreads();
        }
        if (tid == 0) g_sca[t] = red[0] * (1.0f / 256.0f);
    }
}

// ============================================================
// K2: per-(layer, chunk) partial Grams  +  per-(t,n) node covariances
// grid: 256 blocks x 256 threads.
//   blocks 0..127  : Gram partial, t = blk>>4, chunk c = blk&15 (32 features)
//   blocks 128..255: node covariance, (t,n)
// ============================================================
__global__ void k2_grams_covs() {
    int blk = blockIdx.x, tid = threadIdx.x;
    if (blk < 128) {
        int t = blk >> 4, c = blk & 15;
        // transposed smem tiles: St[f][b], rows padded to 68 floats (16B aligned)
        __shared__ __align__(16) float St_s[CF][68];
        __shared__ __align__(16) float St_t[CF][68];
        int fbase = t * FLAYER + c * CF;
        for (int k = tid; k < BB * CF; k += 256) {
            int b = k >> 5, f = k & 31;            // coalesced gmem read
            St_s[f][b] = g_Zc[0][b * FTOT + fbase + f];
            St_t[f][b] = g_Zc[1][b * FTOT + fbase + f];
        }
        __syncthreads();
        int ri = tid & 15, ci = tid >> 4;          // 4x4 output tile per thread
        float a_ss[4][4] = {}, a_tt[4][4] = {}, a_st[4][4] = {};
        #pragma unroll 4
        for (int f = 0; f < CF; f++) {
            float4 v;
            float As[4], Bs[4], At[4], Bt[4];
            v = *(const float4*)&St_s[f][4 * ri]; As[0]=v.x; As[1]=v.y; As[2]=v.z; As[3]=v.w;
            v = *(const float4*)&St_s[f][4 * ci]; Bs[0]=v.x; Bs[1]=v.y; Bs[2]=v.z; Bs[3]=v.w;
            v = *(const float4*)&St_t[f][4 * ri]; At[0]=v.x; At[1]=v.y; At[2]=v.z; At[3]=v.w;
            v = *(const float4*)&St_t[f][4 * ci]; Bt[0]=v.x; Bt[1]=v.y; Bt[2]=v.z; Bt[3]=v.w;
            #pragma unroll
            for (int i = 0; i < 4; i++)
                #pragma unroll
                for (int j = 0; j < 4; j++) {
                    a_ss[i][j] += As[i] * Bs[j];
                    a_tt[i][j] += At[i] * Bt[j];
                    a_st[i][j] += As[i] * Bt[j];
                }
        }
        float* p0 = &g_P[((0 * HL + t) * NCHUNK + c) * 4096];
        float* p1 = &g_P[((1 * HL + t) * NCHUNK + c) * 4096];
        float* p2 = &g_P[((2 * HL + t) * NCHUNK + c) * 4096];
        #pragma unroll
        for (int i = 0; i < 4; i++)
            #pragma unroll
            for (int j = 0; j < 4; j++) {
                int o = (4 * ri + i) * 64 + 4 * ci + j;
                p0[o] = a_ss[i][j];
                p1[o] = a_tt[i][j];
                p2[o] = a_st[i][j];
            }
    } else {
        // node covariances: C[t,n] = Xc^T Xc / 63, Xc = g_Zc[:, t, n, :]  [64 x 32]
        int id = blk - 128;
        int t = id >> 4, n = id & 15;
        __shared__ __align__(16) float Xs[BB * DDIM];
        __shared__ __align__(16) float Xt[BB * DDIM];
        int base = t * FLAYER + n * DDIM;
        for (int k = tid; k < BB * DDIM; k += 256) {
            int b = k >> 5, dd = k & 31;
            Xs[k] = g_Zc[0][b * FTOT + base + dd];
            Xt[k] = g_Zc[1][b * FTOT + base + dd];
        }
        __syncthreads();
        int ai = tid & 15, bi = tid >> 4;          // 2x2 output tile
        float cs[2][2] = {}, ct[2][2] = {};
        #pragma unroll 8
        for (int b = 0; b < BB; b++) {
            float2 va = *(const float2*)&Xs[b * DDIM + 2 * ai];
            float2 vb = *(const float2*)&Xs[b * DDIM + 2 * bi];
            float2 wa = *(const float2*)&Xt[b * DDIM + 2 * ai];
            float2 wb = *(const float2*)&Xt[b * DDIM + 2 * bi];
            cs[0][0] += va.x * vb.x; cs[0][1] += va.x * vb.y;
            cs[1][0] += va.y * vb.x; cs[1][1] += va.y * vb.y;
            ct[0][0] += wa.x * wb.x; ct[0][1] += wa.x * wb.y;
            ct[1][0] += wa.y * wb.x; ct[1][1] += wa.y * wb.y;
        }
        const float inv63 = 1.0f / 63.0f;
        int cbase = (t * NPTS + n) * (DDIM * DDIM);
        #pragma unroll
        for (int i = 0; i < 2; i++)
            #pragma unroll
            for (int j = 0; j < 2; j++) {
                int o = cbase + (2 * ai + i) * DDIM + (2 * bi + j);
                g_C[0][o] = cs[i][j] * inv63;
                g_C[1][o] = ct[i][j] * inv63;
            }
    }
}

// ============================================================
// K3: per-(t,n) contrastive log term  +  Gram chunk reduction / ||G||^2
// grid: 152 blocks x 512 threads.
//   blocks 0..127  : sfa term for (t,n); warp w handles column j=w
//   blocks 128..151: reduce 16 chunk partials for gram g = blk-128 (type*8+t)
// ============================================================
__global__ void k3_sfa_gramred() {
    int blk = blockIdx.x, tid = threadIdx.x;
    if (blk < 128) {
        int t = blk >> 4, n = blk & 15;
        int w = tid >> 5, lane = tid & 31;        // w = j in 0..15
        const float* Cs = &g_C[0][(t * NPTS + n) * (DDIM * DDIM)];
        const float* Ct = &g_C[1][(t * NPTS + w) * (DDIM * DDIM)];
        float dot = 0.f, sqt = 0.f, sqs = 0.f;
        #pragma unroll 8
        for (int k = lane; k < DDIM * DDIM; k += 32) {
            float a = Cs[k], b = Ct[k];
            dot += a * b;
            sqt += b * b;
            sqs += a * a;
        }
        #pragma unroll
        for (int o = 16; o > 0; o >>= 1) {
            dot += __shfl_xor_sync(0xFFFFFFFFu, dot, o);
            sqt += __shfl_xor_sync(0xFFFFFFFFu, sqt, o);
            sqs += __shfl_xor_sync(0xFFFFFFFFu, sqs, o);
        }
        __shared__ float sm_st[16], sm_tt[16], sm_ss;
        if (lane == 0) {
            sm_st[w] = dot;
            sm_tt[w] = sqt;
            if (w == 0) sm_ss = sqs;
        }
        __syncthreads();
        if (tid == 0) {
            float ss = sm_ss;
            float Dsum = 0.f, pos = 0.f;
            #pragma unroll
            for (int j = 0; j < 16; j++) {
                float Dj = (ss + sm_tt[j] - 2.0f * sm_st[j]) * (1.0f / 4096.0f);
                Dsum += Dj;
                if (j == n) pos = Dj;
            }
            float neg = Dsum - pos;
            float ep = expf(pos);
            // -log(ep/(ep+neg+EPS)) = log(ep+neg+EPS) - pos
            g_sfa[t * NPTS + n] = logf(ep + neg + 1e-8f) - pos;
        }
    } else {
        int g = blk - 128;                        // 0..23 == type*8 + t
        const float* Pbase = &g_P[g * NCHUNK * 4096];
        float* Gout = &g_Gram[g * 4096];
        float sq = 0.f;
        for (int i = tid; i < 4096; i += 512) {
            float v = 0.f;
            #pragma unroll
            for (int c = 0; c < NCHUNK; c++) v += Pbase[c * 4096 + i];
            Gout[i] = v;
            sq += v * v;
        }
        __shared__ float red[512];
        red[tid] = sq;
        __syncthreads();
        for (int s2 = 256; s2 > 0; s2 >>= 1) {
            if (tid < s2) red[tid] += red[tid + s2];
            __syncthreads();
        }
        if (tid == 0) g_Wnum[g] = red[0];
    }
}

// ============================================================
// K4: L_exo Gram norms (sum of layer Grams) + final scalar combine
// grid: 1 block x 512 threads
// ============================================================
__global__ void k4_final(float* __restrict__ out) {
    int tid = threadIdx.x;
    float sq0 = 0.f, sq1 = 0.f, sq2 = 0.f;
    for (int i = tid; i < 4096; i += 512) {
        float v0 = 0.f, v1 = 0.f, v2 = 0.f;
        #pragma unroll
        for (int t = 0; t < HL; t++) {
            v0 += g_Gram[(0 * HL + t) * 4096 + i];
            v1 += g_Gram[(1 * HL + t) * 4096 + i];
            v2 += g_Gram[(2 * HL + t) * 4096 + i];
        }
        sq0 += v0 * v0;
        sq1 += v1 * v1;
        sq2 += v2 * v2;
    }
    __shared__ float r0[512], r1[512], r2[512];
    r0[tid] = sq0; r1[tid] = sq1; r2[tid] = sq2;
    __syncthreads();
    for (int s2 = 256; s2 > 0; s2 >>= 1) {
        if (tid < s2) {
            r0[tid] += r0[tid + s2];
            r1[tid] += r1[tid + s2];
            r2[tid] += r2[tid + s2];
        }
        __syncthreads();
    }
    if (tid == 0) {
        // L_exo = (||Gs||^2 + ||Gt||^2 - 2||Gst||^2) / (63^2 * 4 * 4096^2)
        const float exo_scale = (float)(1.0 / (3969.0 * 4.0 * 16777216.0));
        float L_exo = (r0[0] + r1[0] - 2.0f * r2[0]) * exo_scale;
        // W[t] = (...) / (63^2 * 4 * 512^2)
        const float w_scale = (float)(1.0 / (3969.0 * 4.0 * 262144.0));
        float acc = 0.f;
        #pragma unroll
        for (int t = 0; t < HL; t++) {
            float W = (g_Wnum[t] + g_Wnum[HL + t] - 2.0f * g_Wnum[2 * HL + t]) * w_scale;
            float sfa = 0.f;
            #pragma unroll
            for (int n = 0; n < NPTS; n++) sfa += g_sfa[t * NPTS + n];
            sfa *= (1.0f / (float)NPTS);
            acc += W * (0.1f * g_sca[t] + 0.1f * sfa);
        }
        out[0] = L_exo + acc * (1.0f / (float)HL);
    }
}

// ============================================================
extern "C" void kernel_launch(void* const* d_in, const int* in_sizes, int n_in,
                              void* d_out, int out_size) {
    const float* Zs = (const float*)d_in[0];
    const float* Es = (const float*)d_in[1];
    const float* Zt = (const float*)d_in[2];
    const float* Et = (const float*)d_in[3];
    float* out = (float*)d_out;

    k1_center_sca<<<40, 256>>>(Zs, Es, Zt, Et);
    k2_grams_covs<<<256, 256>>>();
    k3_sfa_gramred<<<152, 512>>>();
    k4_final<<<1, 512>>>(out);
}